// round 5
// baseline (speedup 1.0000x reference)
#include <cuda_runtime.h>
#include <cuda_fp16.h>
#include <cstdint>

// ============================================================================
// LearnedClassVectors: bucketize -> embed(13x8 LUT) -> 4x4x4 patch -> FC 512->768
// Fused fp16 GEMM via mma.sync.m16n8k16.
//   M = 65536 patches, K = 512, N = 768, fp32 accumulate.
// R5: CTA tile 128x256, 8 warps (2Mx4N) of 64x64 warp tiles (was 64x32).
//     Cuts smem ldmatrix bytes per FLOP 1.5x -- R4 ncu showed L1=74.9% binding
//     with tensor only 49.4%.
// ============================================================================

static __device__ __forceinline__ uint32_t smem_u32(const void* p) {
    uint32_t a;
    asm("{ .reg .u64 t; cvta.to.shared.u64 t, %1; cvt.u32.u64 %0, t; }"
        : "=r"(a) : "l"(p));
    return a;
}

#define LDS128(r0, r1, r2, r3, addr) \
    asm volatile("ld.shared.v4.u32 {%0, %1, %2, %3}, [%4];" \
                 : "=r"(r0), "=r"(r1), "=r"(r2), "=r"(r3) : "r"(addr))
#define STS128(r0, r1, r2, r3, addr) \
    asm volatile("st.shared.v4.b32 [%0], {%1, %2, %3, %4};" \
                 :: "r"(addr), "r"(r0), "r"(r1), "r"(r2), "r"(r3) : "memory")

#define LDSM_X4(r0, r1, r2, r3, addr) \
    asm volatile("ldmatrix.sync.aligned.m8n8.x4.shared.b16 {%0, %1, %2, %3}, [%4];" \
                 : "=r"(r0), "=r"(r1), "=r"(r2), "=r"(r3) : "r"(addr))
#define LDSM_X2(r0, r1, addr) \
    asm volatile("ldmatrix.sync.aligned.m8n8.x2.shared.b16 {%0, %1}, [%2];" \
                 : "=r"(r0), "=r"(r1) : "r"(addr))

#define MMA16816(c, a, b)                                                     \
    asm volatile(                                                             \
        "mma.sync.aligned.m16n8k16.row.col.f32.f16.f16.f32 "                  \
        "{%0, %1, %2, %3}, {%4, %5, %6, %7}, {%8, %9}, {%0, %1, %2, %3};"     \
        : "+f"((c)[0]), "+f"((c)[1]), "+f"((c)[2]), "+f"((c)[3])              \
        : "r"((a)[0]), "r"((a)[1]), "r"((a)[2]), "r"((a)[3]),                 \
          "r"((b)[0]), "r"((b)[1]))

#define CP_ASYNC16(dst, src) \
    asm volatile("cp.async.cg.shared.global [%0], [%1], 16;" \
                 :: "r"(dst), "l"(src) : "memory")
#define CP_COMMIT()  asm volatile("cp.async.commit_group;" ::: "memory")
#define CP_WAIT0()   asm volatile("cp.async.wait_group 0;" ::: "memory")

// SW128 swizzle: byte = row*128 + koff (koff < 128)
static __device__ __forceinline__ uint32_t swz(uint32_t base, uint32_t row, uint32_t koff) {
    return base + row * 128u + (koff ^ ((row & 7u) * 16u));
}

// ---------------- problem constants ----------------
static constexpr int N_TOTAL = 768;
static constexpr int K_TOTAL = 512;
static constexpr int NSTAGES = 8;             // K / 64
static constexpr int N_TILES = 3;             // 768 / 256
static constexpr int M_TILES = 512;

// SMEM layout
static constexpr int SMEM_LUT = 0;                    // 13 x 16B fp16 vectors
static constexpr int SMEM_A0  = 1024;                 // 128 x 128B = 16 KB
static constexpr int SMEM_A1  = SMEM_A0 + 16384;
static constexpr int SMEM_B0  = SMEM_A1 + 16384;      // 256 x 128B = 32 KB
static constexpr int SMEM_B1  = SMEM_B0 + 32768;
static constexpr int SMEM_BYTES = SMEM_B1 + 32768;    // 99328

// fp16 copy of fc_w [768][512]
__device__ __align__(16) __half g_Wh[N_TOTAL * K_TOTAL];

__global__ void __launch_bounds__(256) convert_w_kernel(const float* __restrict__ w)
{
    int i = (blockIdx.x * 256 + threadIdx.x) * 4;
    if (i < N_TOTAL * K_TOTAL) {
        float4 v = *reinterpret_cast<const float4*>(w + i);
        __half2* p = reinterpret_cast<__half2*>(g_Wh + i);
        p[0] = __floats2half2_rn(v.x, v.y);
        p[1] = __floats2half2_rn(v.z, v.w);
    }
}

// bucket = count(x >= iv_i)  ==  searchsorted(side='right')
static __device__ __forceinline__ int hu_bucket(float v)
{
    int b = 0;
    b += (v >= -1000.0f); b += (v >= -900.0f); b += (v >= -400.0f);
    b += (v >= -100.0f);  b += (v >= -50.0f);  b += (v >= -10.0f);
    b += (v >= 20.0f);    b += (v >= 40.0f);   b += (v >= 60.0f);
    b += (v >= 100.0f);   b += (v >= 800.0f);  b += (v >= 1000.0f);
    return b;
}

// ---------------- main fused kernel ----------------
__global__ void __launch_bounds__(256, 1) lcv_gemm_kernel(
    const float* __restrict__ x,        // [2,1,128,128,128]
    const float* __restrict__ vectors,  // [13,8]
    const float* __restrict__ fc_b,     // [768]
    float* __restrict__ out)            // [2,768,32,32,32]
{
    extern __shared__ __align__(1024) char smem[];
    const uint32_t sb = smem_u32(smem);
    const int tid = threadIdx.x;
    const int lane = tid & 31;
    const int warp = tid >> 5;

    // nt fastest so the 3 CTAs sharing an x-slice are L2-adjacent
    const int nt = blockIdx.x % N_TILES;
    const int mt = blockIdx.x / N_TILES;
    const int m0 = mt << 7;              // first patch of tile
    const int n0 = nt << 8;              // first output channel of tile (256-wide)
    const int bidx = m0 >> 15;           // batch
    const int s0 = m0 & 32767;           // spatial offset gd*1024+gh*32+gw
    const int gd = s0 >> 10;
    const int gh0 = (s0 >> 5) & 31;

    // warp layout: 2 (M) x 4 (N); warp tile 64 x 64
    const int warp_m = (warp >> 2) * 64;   // 0 or 64
    const int warp_n = (warp & 3) * 64;    // 0..192

    // vectors LUT -> fp16 smem (13 rows x 16B)
    if (tid < 104) {
        __half h = __float2half_rn(vectors[tid]);
        *reinterpret_cast<__half*>(smem + SMEM_LUT + (tid >> 3) * 16 + (tid & 7) * 2) = h;
    }
    __syncthreads();

    const uint32_t a_off[2] = {SMEM_A0, SMEM_A1};
    const uint32_t b_off[2] = {SMEM_B0, SMEM_B1};
    const uint32_t lut_base = sb + SMEM_LUT;

    // ---- A-build mapping: thread owns patch-row r, one ph of the stage pair
    const int r = tid >> 1;              // 0..127
    const int ph_off = tid & 1;
    const int gh = gh0 + (r >> 5);
    const int gw = r & 31;
    const float* xb = x + (size_t)bidx * 2097152;

    // ---- ldmatrix per-lane constants
    const uint32_t a_row_l = (uint32_t)(warp_m + (lane & 7) + ((lane >> 3) & 1) * 8);
    const uint32_t a_kc16  = (uint32_t)((lane >> 4) * 16);
    const int l2 = lane & 15;
    const uint32_t b_row_l = (uint32_t)(warp_n + (l2 & 7));
    const uint32_t b_kc16  = (uint32_t)((l2 >> 3) * 16);

    float acc4[4][8][4];
    #pragma unroll
    for (int mi = 0; mi < 4; mi++)
        #pragma unroll
        for (int ni = 0; ni < 8; ni++)
            #pragma unroll
            for (int k = 0; k < 4; k++) acc4[mi][ni][k] = 0.0f;

    // ---------- stage 0 prologue ----------
    {
        // A(0): stage 0 -> pd=0, ph=ph_off
        const int d = gd << 2;
        const int h = (gh << 2) + ph_off;
        const float4 xv = *reinterpret_cast<const float4*>(
            xb + ((size_t)d << 14) + (h << 7) + (gw << 2));
        const uint32_t abase = sb + a_off[0];
        float vox[4] = {xv.x, xv.y, xv.z, xv.w};
        #pragma unroll
        for (int pw = 0; pw < 4; pw++) {
            int bkt = hu_bucket(vox[pw]);
            uint32_t q0, q1, q2, q3;
            LDS128(q0, q1, q2, q3, lut_base + (uint32_t)bkt * 16);
            STS128(q0, q1, q2, q3,
                   swz(abase, (uint32_t)r, (uint32_t)(ph_off * 64 + pw * 16)));
        }
        // B(0): 256 rows x 128B via cp.async (2048 x 16B chunks)
        const uint32_t bbase = sb + b_off[0];
        #pragma unroll
        for (int i = 0; i < 8; i++) {
            int idx = tid + (i << 8);
            uint32_t brow = (uint32_t)(idx >> 3);
            uint32_t bkc  = (uint32_t)(idx & 7);
            const __half* src = g_Wh + (size_t)(n0 + brow) * K_TOTAL + bkc * 8;
            CP_ASYNC16(swz(bbase, brow, bkc * 16), src);
        }
        CP_COMMIT();
        CP_WAIT0();
        __syncthreads();
    }

    // ---------- main loop over 8 K-stages of 64 ----------
    int buf = 0;
    for (int ks = 0; ks < NSTAGES; ks++) {
        const int nbuf = buf ^ 1;
        float vox[4];
        const bool more = (ks + 1 < NSTAGES);

        // issue next-stage global loads early (latency hides under the MMAs)
        if (more) {
            const int ks1 = ks + 1;
            const int pd = ks1 >> 1;
            const int ph = ((ks1 & 1) << 1) + ph_off;
            const int d = (gd << 2) + pd;
            const int h = (gh << 2) + ph;
            const float4 xv = *reinterpret_cast<const float4*>(
                xb + ((size_t)d << 14) + (h << 7) + (gw << 2));
            vox[0] = xv.x; vox[1] = xv.y; vox[2] = xv.z; vox[3] = xv.w;

            const uint32_t bbase = sb + b_off[nbuf];
            const int k0 = ks1 << 6;
            #pragma unroll
            for (int i = 0; i < 8; i++) {
                int idx = tid + (i << 8);
                uint32_t brow = (uint32_t)(idx >> 3);
                uint32_t bkc  = (uint32_t)(idx & 7);
                const __half* src = g_Wh + (size_t)(n0 + brow) * K_TOTAL + k0 + bkc * 8;
                CP_ASYNC16(swz(bbase, brow, bkc * 16), src);
            }
            CP_COMMIT();
        }

        // ---- compute this stage: 4 k-steps of 16 ----
        const uint32_t abase = sb + a_off[buf];
        const uint32_t bbase = sb + b_off[buf];
        #pragma unroll
        for (int ks16 = 0; ks16 < 4; ks16++) {
            const uint32_t koffA = (uint32_t)(ks16 * 32) + a_kc16;
            const uint32_t koffB = (uint32_t)(ks16 * 32) + b_kc16;
            uint32_t af[4][4];
            #pragma unroll
            for (int mi = 0; mi < 4; mi++) {
                LDSM_X4(af[mi][0], af[mi][1], af[mi][2], af[mi][3],
                        swz(abase, a_row_l + (uint32_t)(mi * 16), koffA));
            }
            #pragma unroll
            for (int ni = 0; ni < 8; ni++) {
                uint32_t bf[2];
                LDSM_X2(bf[0], bf[1],
                        swz(bbase, b_row_l + (uint32_t)(ni * 8), koffB));
                #pragma unroll
                for (int mi = 0; mi < 4; mi++)
                    MMA16816(acc4[mi][ni], af[mi], bf);
            }
        }

        // finish next-stage A build, drain cp.async, flip buffers
        if (more) {
            const uint32_t anext = sb + a_off[nbuf];
            #pragma unroll
            for (int pw = 0; pw < 4; pw++) {
                int bkt = hu_bucket(vox[pw]);
                uint32_t q0, q1, q2, q3;
                LDS128(q0, q1, q2, q3, lut_base + (uint32_t)bkt * 16);
                STS128(q0, q1, q2, q3,
                       swz(anext, (uint32_t)r, (uint32_t)(ph_off * 64 + pw * 16)));
            }
            CP_WAIT0();
            __syncthreads();
        }
        buf = nbuf;
    }

    // ---------- epilogue ----------
    // fragment c0=(m=l/4, n=2(l%4)), c1=(m, n+1), c2=(m+8, n), c3=(m+8, n+1)
    {
        float* ob = out + (size_t)bidx * N_TOTAL * 32768 + (size_t)s0;
        const int mrow = warp_m + (lane >> 2);
        const int ncol = n0 + warp_n + 2 * (lane & 3);
        #pragma unroll
        for (int mi = 0; mi < 4; mi++) {
            const int m_t = mrow + mi * 16;
            #pragma unroll
            for (int ni = 0; ni < 8; ni++) {
                const int o0 = ncol + ni * 8;
                const float2 bv = *reinterpret_cast<const float2*>(fc_b + o0);
                ob[(size_t)o0 * 32768 + m_t]           = acc4[mi][ni][0] + bv.x;
                ob[(size_t)(o0 + 1) * 32768 + m_t]     = acc4[mi][ni][1] + bv.y;
                ob[(size_t)o0 * 32768 + m_t + 8]       = acc4[mi][ni][2] + bv.x;
                ob[(size_t)(o0 + 1) * 32768 + m_t + 8] = acc4[mi][ni][3] + bv.y;
            }
        }
    }
}

// ---------------- launch ----------------
extern "C" void kernel_launch(void* const* d_in, const int* in_sizes, int n_in,
                              void* d_out, int out_size)
{
    (void)in_sizes; (void)n_in; (void)out_size;
    const float* x       = (const float*)d_in[0];  // [2,1,128,128,128]
    const float* vectors = (const float*)d_in[1];  // [13,8]
    const float* fc_w    = (const float*)d_in[2];  // [768,512]
    const float* fc_b    = (const float*)d_in[3];  // [768]
    float* out = (float*)d_out;                    // [2,768,32,32,32]

    cudaFuncSetAttribute(lcv_gemm_kernel,
                         cudaFuncAttributeMaxDynamicSharedMemorySize, SMEM_BYTES);

    convert_w_kernel<<<(N_TOTAL * K_TOTAL / 4 + 255) / 256, 256>>>(fc_w);
    lcv_gemm_kernel<<<M_TILES * N_TILES, 256, SMEM_BYTES>>>(x, vectors, fc_b, out);
}

// round 6
// speedup vs baseline: 1.0873x; 1.0873x over previous
#include <cuda_runtime.h>
#include <cuda_fp16.h>
#include <cstdint>

// ============================================================================
// LearnedClassVectors fused fp16 GEMM (M=65536, K=512, N=768), mma.sync.
// R6: back to R4 shape (CTA 128x128, 8 warps 2x4, warp tile 64x32, 2 CTAs/SM)
//     but B comes straight from L2 via one coalesced LDG.64 per fragment
//     (fragment-native weight layout g_Wf). Removes B smem + cp.async + B
//     ldmatrix -> L1 traffic/stage 130KB -> 82KB. R4 was L1-bound (74.9%).
// ============================================================================

static __device__ __forceinline__ uint32_t smem_u32(const void* p) {
    uint32_t a;
    asm("{ .reg .u64 t; cvta.to.shared.u64 t, %1; cvt.u32.u64 %0, t; }"
        : "=r"(a) : "l"(p));
    return a;
}

#define LDS128(r0, r1, r2, r3, addr) \
    asm volatile("ld.shared.v4.u32 {%0, %1, %2, %3}, [%4];" \
                 : "=r"(r0), "=r"(r1), "=r"(r2), "=r"(r3) : "r"(addr))
#define STS128(r0, r1, r2, r3, addr) \
    asm volatile("st.shared.v4.b32 [%0], {%1, %2, %3, %4};" \
                 :: "r"(addr), "r"(r0), "r"(r1), "r"(r2), "r"(r3) : "memory")

#define LDSM_X4(r0, r1, r2, r3, addr) \
    asm volatile("ldmatrix.sync.aligned.m8n8.x4.shared.b16 {%0, %1, %2, %3}, [%4];" \
                 : "=r"(r0), "=r"(r1), "=r"(r2), "=r"(r3) : "r"(addr))

#define MMA16816S(c, a, b0, b1)                                               \
    asm volatile(                                                             \
        "mma.sync.aligned.m16n8k16.row.col.f32.f16.f16.f32 "                  \
        "{%0, %1, %2, %3}, {%4, %5, %6, %7}, {%8, %9}, {%0, %1, %2, %3};"     \
        : "+f"((c)[0]), "+f"((c)[1]), "+f"((c)[2]), "+f"((c)[3])              \
        : "r"((a)[0]), "r"((a)[1]), "r"((a)[2]), "r"((a)[3]),                 \
          "r"(b0), "r"(b1))

// SW128 swizzle for the A tile (128B rows)
static __device__ __forceinline__ uint32_t swz(uint32_t base, uint32_t row, uint32_t koff) {
    return base + row * 128u + (koff ^ ((row & 7u) * 16u));
}

// ---------------- problem constants ----------------
static constexpr int N_TOTAL = 768;
static constexpr int K_TOTAL = 512;
static constexpr int N_TILES = 6;             // 768 / 128
static constexpr int M_TILES = 512;

// SMEM: LUT + double-buffered A only (B never touches smem)
static constexpr int SMEM_LUT = 0;                    // 13 x 16B fp16 vectors
static constexpr int SMEM_A0  = 1024;                 // 128 x 128B = 16 KB
static constexpr int SMEM_A1  = SMEM_A0 + 16384;
static constexpr int SMEM_BYTES = SMEM_A1 + 16384;    // 33792

// Fragment-native fp16 weights: blocks (bn in 0..95, bk in 0..31), each block
// = 8n x 16k, stored as 32 lanes x uint2 where lane l of block (bn,bk) holds
//   b0 = {w[n][k0+2j], w[n][k0+2j+1]},  b1 = {w[n][k0+2j+8], w[n][k0+2j+9]}
// with n = bn*8 + l/4, j = l%4, k0 = bk*16. Exactly the m16n8k16 B fragment.
__device__ __align__(16) uint2 g_Wf[96 * 32 * 32];

__global__ void __launch_bounds__(256) convert_w_kernel(const float* __restrict__ w)
{
    const int idx = blockIdx.x * 256 + threadIdx.x;     // 0 .. 98303
    const int l   = idx & 31;
    const int blk = idx >> 5;                           // bn*32 + bk
    const int bk  = blk & 31;
    const int bn  = blk >> 5;
    const int n   = bn * 8 + (l >> 2);
    const int k0  = bk * 16 + 2 * (l & 3);
    const float* wr = w + (size_t)n * K_TOTAL + k0;
    __half2 p0 = __floats2half2_rn(wr[0], wr[1]);
    __half2 p1 = __floats2half2_rn(wr[8], wr[9]);
    uint2 v;
    v.x = *reinterpret_cast<uint32_t*>(&p0);
    v.y = *reinterpret_cast<uint32_t*>(&p1);
    g_Wf[idx] = v;
}

// bucket = count(x >= iv_i)  ==  searchsorted(side='right')
static __device__ __forceinline__ int hu_bucket(float v)
{
    int b = 0;
    b += (v >= -1000.0f); b += (v >= -900.0f); b += (v >= -400.0f);
    b += (v >= -100.0f);  b += (v >= -50.0f);  b += (v >= -10.0f);
    b += (v >= 20.0f);    b += (v >= 40.0f);   b += (v >= 60.0f);
    b += (v >= 100.0f);   b += (v >= 800.0f);  b += (v >= 1000.0f);
    return b;
}

// ---------------- main fused kernel ----------------
__global__ void __launch_bounds__(256, 2) lcv_gemm_kernel(
    const float* __restrict__ x,        // [2,1,128,128,128]
    const float* __restrict__ vectors,  // [13,8]
    const float* __restrict__ fc_b,     // [768]
    float* __restrict__ out)            // [2,768,32,32,32]
{
    extern __shared__ __align__(1024) char smem[];
    const uint32_t sb = smem_u32(smem);
    const int tid = threadIdx.x;
    const int lane = tid & 31;
    const int warp = tid >> 5;

    // nt fastest so the 6 CTAs sharing an x-slice are L2-adjacent
    const int nt = blockIdx.x % N_TILES;
    const int mt = blockIdx.x / N_TILES;
    const int m0 = mt << 7;
    const int n0 = nt << 7;
    const int bidx = m0 >> 15;
    const int s0 = m0 & 32767;
    const int gd = s0 >> 10;
    const int gh0 = (s0 >> 5) & 31;

    // warp layout: 2 (M) x 4 (N); warp tile 64 x 32
    const int warp_m = (warp >> 2) * 64;
    const int warp_n = (warp & 3) * 32;

    // vectors LUT -> fp16 smem (13 rows x 16B)
    if (tid < 104) {
        __half h = __float2half_rn(vectors[tid]);
        *reinterpret_cast<__half*>(smem + SMEM_LUT + (tid >> 3) * 16 + (tid & 7) * 2) = h;
    }

    const uint32_t a_off[2] = {SMEM_A0, SMEM_A1};
    const uint32_t lut_base = sb + SMEM_LUT;

    // A-build mapping: thread owns patch-row r, one ph of the stage pair
    const int r = tid >> 1;
    const int ph_off = tid & 1;
    const int gh = gh0 + (r >> 5);
    const int gw = r & 31;
    const float* xb = x + (size_t)bidx * 2097152;

    // A ldmatrix per-lane constants
    const uint32_t a_row_l = (uint32_t)(warp_m + (lane & 7) + ((lane >> 3) & 1) * 8);
    const uint32_t a_kc16  = (uint32_t)((lane >> 4) * 16);

    // B fragment pointer: blocks bn = n0/8 + (warp&3)*4 + ni, bk = kk
    // uint2 offset = (bn*32 + bk)*32 + lane
    const uint2* bp = g_Wf + ((size_t)(n0 / 8 + (warp & 3) * 4) * 32) * 32 + lane;
    // ni stride = 1024 uint2, kk stride = 32 uint2

    float acc4[4][4][4];
    #pragma unroll
    for (int mi = 0; mi < 4; mi++)
        #pragma unroll
        for (int ni = 0; ni < 4; ni++)
            #pragma unroll
            for (int k = 0; k < 4; k++) acc4[mi][ni][k] = 0.0f;

    __syncthreads();   // LUT visible

    // ---------- prologue: build A(stage 0) ----------
    {
        const int d = gd << 2;
        const int h = (gh << 2) + ph_off;
        const float4 xv = *reinterpret_cast<const float4*>(
            xb + ((size_t)d << 14) + (h << 7) + (gw << 2));
        const uint32_t abase = sb + a_off[0];
        float vox0[4] = {xv.x, xv.y, xv.z, xv.w};
        #pragma unroll
        for (int pw = 0; pw < 4; pw++) {
            int bkt = hu_bucket(vox0[pw]);
            uint32_t q0, q1, q2, q3;
            LDS128(q0, q1, q2, q3, lut_base + (uint32_t)bkt * 16);
            STS128(q0, q1, q2, q3,
                   swz(abase, (uint32_t)r, (uint32_t)(ph_off * 64 + pw * 16)));
        }
        __syncthreads();
    }

    // B prefetch for kk=0
    uint2 bf[2][4];
    #pragma unroll
    for (int ni = 0; ni < 4; ni++)
        bf[0][ni] = __ldg(bp + (size_t)ni * 1024);

    // ---------- main loop: 8 A-stages x 4 k16-steps ----------
    int buf = 0;
    for (int ks = 0; ks < 8; ks++) {
        const bool more = (ks + 1 < 8);
        float vox[4];

        // issue next-stage x load early (~3 k16-steps of latency cover)
        if (more) {
            const int ks1 = ks + 1;
            const int pd = ks1 >> 1;
            const int ph = ((ks1 & 1) << 1) + ph_off;
            const int d = (gd << 2) + pd;
            const int h = (gh << 2) + ph;
            const float4 xv = *reinterpret_cast<const float4*>(
                xb + ((size_t)d << 14) + (h << 7) + (gw << 2));
            vox[0] = xv.x; vox[1] = xv.y; vox[2] = xv.z; vox[3] = xv.w;
        }

        const uint32_t abase = sb + a_off[buf];
        #pragma unroll
        for (int q = 0; q < 4; q++) {
            const int kk = ks * 4 + q;
            const int cur = kk & 1;
            // prefetch B fragments for kk+1
            if (kk + 1 < 32) {
                #pragma unroll
                for (int ni = 0; ni < 4; ni++)
                    bf[cur ^ 1][ni] = __ldg(bp + (size_t)ni * 1024 + (size_t)(kk + 1) * 32);
            }
            // A fragments for this k16
            const uint32_t koffA = (uint32_t)(q * 32) + a_kc16;
            uint32_t af[4][4];
            #pragma unroll
            for (int mi = 0; mi < 4; mi++) {
                LDSM_X4(af[mi][0], af[mi][1], af[mi][2], af[mi][3],
                        swz(abase, a_row_l + (uint32_t)(mi * 16), koffA));
            }
            #pragma unroll
            for (int ni = 0; ni < 4; ni++) {
                const uint32_t b0 = bf[cur][ni].x;
                const uint32_t b1 = bf[cur][ni].y;
                #pragma unroll
                for (int mi = 0; mi < 4; mi++)
                    MMA16816S(acc4[mi][ni], af[mi], b0, b1);
            }
        }

        // build next A stage, flip
        if (more) {
            const uint32_t anext = sb + a_off[buf ^ 1];
            #pragma unroll
            for (int pw = 0; pw < 4; pw++) {
                int bkt = hu_bucket(vox[pw]);
                uint32_t q0, q1, q2, q3;
                LDS128(q0, q1, q2, q3, lut_base + (uint32_t)bkt * 16);
                STS128(q0, q1, q2, q3,
                       swz(anext, (uint32_t)r, (uint32_t)(ph_off * 64 + pw * 16)));
            }
            __syncthreads();
            buf ^= 1;
        }
    }

    // ---------- epilogue ----------
    // fragment c0=(m=l/4, n=2(l%4)), c1=(m, n+1), c2=(m+8, n), c3=(m+8, n+1)
    {
        float* ob = out + (size_t)bidx * N_TOTAL * 32768 + (size_t)s0;
        const int mrow = warp_m + (lane >> 2);
        const int ncol = n0 + warp_n + 2 * (lane & 3);
        #pragma unroll
        for (int mi = 0; mi < 4; mi++) {
            const int m_t = mrow + mi * 16;
            #pragma unroll
            for (int ni = 0; ni < 4; ni++) {
                const int o0 = ncol + ni * 8;
                const float2 bv = *reinterpret_cast<const float2*>(fc_b + o0);
                ob[(size_t)o0 * 32768 + m_t]           = acc4[mi][ni][0] + bv.x;
                ob[(size_t)(o0 + 1) * 32768 + m_t]     = acc4[mi][ni][1] + bv.y;
                ob[(size_t)o0 * 32768 + m_t + 8]       = acc4[mi][ni][2] + bv.x;
                ob[(size_t)(o0 + 1) * 32768 + m_t + 8] = acc4[mi][ni][3] + bv.y;
            }
        }
    }
}

// ---------------- launch ----------------
extern "C" void kernel_launch(void* const* d_in, const int* in_sizes, int n_in,
                              void* d_out, int out_size)
{
    (void)in_sizes; (void)n_in; (void)out_size;
    const float* x       = (const float*)d_in[0];  // [2,1,128,128,128]
    const float* vectors = (const float*)d_in[1];  // [13,8]
    const float* fc_w    = (const float*)d_in[2];  // [768,512]
    const float* fc_b    = (const float*)d_in[3];  // [768]
    float* out = (float*)d_out;                    // [2,768,32,32,32]

    cudaFuncSetAttribute(lcv_gemm_kernel,
                         cudaFuncAttributeMaxDynamicSharedMemorySize, SMEM_BYTES);

    convert_w_kernel<<<96 * 32 * 32 / 256, 256>>>(fc_w);
    lcv_gemm_kernel<<<M_TILES * N_TILES, 256, SMEM_BYTES>>>(x, vectors, fc_b, out);
}